// round 17
// baseline (speedup 1.0000x reference)
#include <cuda_runtime.h>

// x_ref, x : [B=4, C=3, H=512, W=512] float32
// out: [4,3,512,512] f32 (3145728) then best_shifts [4,2] as floats (8)

#define NIMG   12
#define HH     512
#define WW     512
#define W4     (WW/4)
#define NSHIFT 81
#define IMG_ELEMS (HH*WW)
#define OUT_IMG   (NIMG*IMG_ELEMS)
#define NROWBLK 768          // 12 imgs * 64 row-blocks (8 rows each)
#define NDXG    3
#define NBLK    (NROWBLK*NDXG)   // 2304
#define BLK_PER_BATCH 192    // 3 imgs * 64 row-blocks per batch

__device__ float g_partial[NROWBLK * NSHIFT];
__device__ int2  g_best[4];

// ---------------------------------------------------------------------------
// Phase 1: 81-shift correlation; 3 dx per block; all LDG.128 coalesced
// (16B lane stride). Thread: 4 rows x 4 cols; 9 accumulators;
// 432 FMAs/thread. Ref window = 12 floats = 3 coalesced float4 loads/row,
// consumed immediately (ref-ordered) -> ~50 live regs.
// Block = 256 thr = 2 rowgroups(4 rows) x 128 strips; covers 8 image rows.
// Reduction: warp butterfly -> wsum[3][8][9] -> fixed-order sum (determin.).
// ---------------------------------------------------------------------------
__global__ void __launch_bounds__(256) corr_kernel(const float* __restrict__ x,
                                                   const float* __restrict__ xref) {
    __shared__ float wsum[NDXG][8][9];

    int t     = threadIdx.x;
    int b     = blockIdx.x % NROWBLK;            // row-block id
    int dxg   = blockIdx.x / NROWBLK;            // 0..2
    int img   = b >> 6;                          // 64 row-blocks per image
    int rowblk= b & 63;
    int strip = t & 127;                         // 4-col strip (0..127)
    int rgrp  = t >> 7;                          // 0..1
    int a0    = rowblk * 8 + rgrp * 4;           // first of 4 image rows
    int lane  = t & 31;
    int wid   = t >> 5;                          // 0..7

    // preload x strip: 4 rows x 4 cols — one coalesced float4 per row
    const float4* xp4 = (const float4*)x + ((size_t)img << 16);
    float xv[16];
#pragma unroll
    for (int r = 0; r < 4; r++) {
        float4 m = __ldg(xp4 + (a0 + r) * W4 + strip);
        xv[r * 4 + 0] = m.x; xv[r * 4 + 1] = m.y;
        xv[r * 4 + 2] = m.z; xv[r * 4 + 3] = m.w;
    }

    const bool leftok  = (strip != 0);
    const bool rightok = (strip != 127);
    const float4 z4 = make_float4(0.f, 0.f, 0.f, 0.f);
    const float4* ref4 = (const float4*)xref + ((size_t)img << 16);

#pragma unroll 1
    for (int dxi = 0; dxi < NDXG; dxi++) {
        int dx = dxg * NDXG + dxi;
        float acc[9];
#pragma unroll
        for (int d = 0; d < 9; d++) acc[d] = 0.0f;

#pragma unroll
        for (int r = 0; r < 4; r++) {
            int ar = a0 + r + dx - 4;                 // warp-uniform ref row
            bool rok = (unsigned)ar < (unsigned)HH;
            // window cols [j0-4, j0+8) = 3 coalesced float4 at strip-1
            const float4* rp = ref4 + ar * W4 + strip - 1;
            float4 q0 = (rok && leftok)  ? __ldg(rp + 0) : z4;   // k 0..3
            float4 q1 =  rok             ? __ldg(rp + 1) : z4;   // k 4..7
            float4 q2 = (rok && rightok) ? __ldg(rp + 2) : z4;   // k 8..11
            float rv[12] = {q0.x, q0.y, q0.z, q0.w,
                            q1.x, q1.y, q1.z, q1.w,
                            q2.x, q2.y, q2.z, q2.w};
            // ref-ordered: acc[d] += xv[k-d] * rv[k], p = k-d in [0,4)
#pragma unroll
            for (int k = 0; k < 12; k++) {
                const int dlo = (k - 3 < 0) ? 0 : k - 3;
                const int dhi = (k < 8) ? k : 8;
#pragma unroll
                for (int d = dlo; d <= dhi; d++) {
                    acc[d] += xv[r * 4 + (k - d)] * rv[k];
                }
            }
        }

        // warp butterfly per dy; lane d stores warp-total of acc[d]
#pragma unroll
        for (int d = 0; d < 9; d++) {
            float v = acc[d];
            v += __shfl_xor_sync(0xffffffffu, v, 16);
            v += __shfl_xor_sync(0xffffffffu, v, 8);
            v += __shfl_xor_sync(0xffffffffu, v, 4);
            v += __shfl_xor_sync(0xffffffffu, v, 2);
            v += __shfl_xor_sync(0xffffffffu, v, 1);
            if (lane == d) wsum[dxi][wid][d] = v;
        }
    }
    __syncthreads();

    // deterministic fixed-order sum over 8 warps; write 27-shift slice
    if (t < NDXG * 9) {
        int dxi = t / 9;
        int d   = t - dxi * 9;
        float s = 0.0f;
#pragma unroll
        for (int w = 0; w < 8; w++) s += wsum[dxi][w][d];
        g_partial[b * NSHIFT + (dxg * NDXG + dxi) * 9 + d] = s;
    }
}

// ---------------------------------------------------------------------------
// Phase 2: deterministic reduce of 192 partials per (batch,shift) + argmax
// (first-max tie-break, matching jnp.argmax).
// ---------------------------------------------------------------------------
__global__ void __launch_bounds__(384) reduce_argmax_kernel(float* __restrict__ d_out,
                                                            int out_size) {
    __shared__ float sims[4 * NSHIFT];
    int t = threadIdx.x;
    if (t < 4 * NSHIFT) {
        int b = t / NSHIFT;
        int s = t - b * NSHIFT;
        const float* pp = g_partial + (size_t)b * BLK_PER_BATCH * NSHIFT + s;
        float acc = 0.0f;
#pragma unroll 8
        for (int i = 0; i < BLK_PER_BATCH; i++) acc += pp[i * NSHIFT];
        sims[t] = acc;
    }
    __syncthreads();

    int w = t >> 5, lane = t & 31;
    if (w < 4) {
        float bv = -3.0e38f;
        int bi = NSHIFT;
        for (int s = lane; s < NSHIFT; s += 32) {
            float v = sims[w * NSHIFT + s];
            if (v > bv || (v == bv && s < bi)) { bv = v; bi = s; }
        }
#pragma unroll
        for (int off = 16; off; off >>= 1) {
            float ov = __shfl_xor_sync(0xffffffffu, bv, off);
            int   oi = __shfl_xor_sync(0xffffffffu, bi, off);
            if (ov > bv || (ov == bv && oi < bi)) { bv = ov; bi = oi; }
        }
        if (lane == 0) {
            int sx = bi / 9 - 4;
            int sy = bi % 9 - 4;
            g_best[w] = make_int2(sx, sy);
            if (out_size >= OUT_IMG + 8) {
                d_out[OUT_IMG + w * 2 + 0] = (float)sx;
                d_out[OUT_IMG + w * 2 + 1] = (float)sy;
            }
        }
    }
}

// ---------------------------------------------------------------------------
// Phase 3: apply best shift. 4 floats per thread: 2 aligned LDG.128 +
// warp-uniform extract -> 1 STG.128.  (Best measured variant.)
// ---------------------------------------------------------------------------
__global__ void __launch_bounds__(256) apply_kernel(const float* __restrict__ x,
                                                    float* __restrict__ out) {
    int t = blockIdx.x * 256 + threadIdx.x;      // float4 index
    int base = t << 2;
    int j0  = base & 511;
    int i   = (base >> 9) & 511;
    int img = base >> 18;
    int b   = img / 3;
    int2 s  = g_best[b];
    int si  = i - s.x;
    float4 v = make_float4(0.f, 0.f, 0.f, 0.f);
    if ((unsigned)si < (unsigned)HH) {
        int sj  = j0 - s.y;
        int sa  = sj & ~3;
        int off = sj & 3;                        // warp-uniform
        const float* row = x + ((size_t)img << 18) + (si << 9);
        float4 qa = ((unsigned)sa < (unsigned)WW)
                        ? __ldg((const float4*)(row + sa)) : v;
        float4 qb = ((unsigned)(sa + 4) < (unsigned)WW)
                        ? __ldg((const float4*)(row + sa + 4)) : v;
        switch (off) {
            case 0:  v = qa; break;
            case 1:  v = make_float4(qa.y, qa.z, qa.w, qb.x); break;
            case 2:  v = make_float4(qa.z, qa.w, qb.x, qb.y); break;
            default: v = make_float4(qa.w, qb.x, qb.y, qb.z); break;
        }
    }
    ((float4*)out)[t] = v;
}

// ---------------------------------------------------------------------------
extern "C" void kernel_launch(void* const* d_in, const int* in_sizes, int n_in,
                              void* d_out, int out_size) {
    const float* x_ref = (const float*)d_in[0];
    const float* x     = (const float*)d_in[1];
    float* out = (float*)d_out;

    corr_kernel<<<NBLK, 256>>>(x, x_ref);
    reduce_argmax_kernel<<<1, 384>>>(out, out_size);
    apply_kernel<<<OUT_IMG / 4 / 256, 256>>>(x, out);
}